// round 3
// baseline (speedup 1.0000x reference)
#include <cuda_runtime.h>
#include <stdint.h>
#include <math.h>

// ===== problem dims =====
#define Bdim 512
#define Tdim 256
#define Hdim 512
#define NCdim 512
#define SKELdim 256
#define GENdim 16
#define H3dim 1536

#define NBLK 128   // persistent blocks (<= SM count, guaranteed co-resident)
#define NTHR 256

// JAX PRNG: threefry_partitionable (default JAX >= 0.5).
//   split:      key_t = threefry((0,42), (0, t))
//   32-bit bits for flat index j: (x0, x1) = threefry(key_t, (0, j)); bits = x0 ^ x1
// Fallbacks if rel_err is O(1): bits = x0 only, or legacy halves scheme.
#define BITS_FOLD_XOR 1

// ===== persistent device state =====
__device__ float g_h1[Bdim * Hdim];
__device__ float g_h2[Bdim * Hdim];
__device__ float g_gi[Bdim * H3dim];
__device__ float g_gh[Bdim * H3dim];
__device__ int   g_tok[Bdim];
__device__ unsigned g_key0[Tdim];
__device__ unsigned g_key1[Tdim];
__device__ unsigned g_bar_count;           // zero-init; returns to 0 after each full barrier
__device__ volatile unsigned g_bar_gen;    // monotonically increasing across replays (ok)

// ===== threefry2x32 =====
__device__ __forceinline__ void threefry2x32(unsigned k0, unsigned k1,
                                             unsigned c0, unsigned c1,
                                             unsigned& o0, unsigned& o1) {
    unsigned ks2 = k0 ^ k1 ^ 0x1BD11BDAu;
    unsigned x0 = c0 + k0;
    unsigned x1 = c1 + k1;
#define TF_RND(r) { x0 += x1; x1 = (x1 << (r)) | (x1 >> (32 - (r))); x1 ^= x0; }
    TF_RND(13) TF_RND(15) TF_RND(26) TF_RND(6)
    x0 += k1;  x1 += ks2 + 1u;
    TF_RND(17) TF_RND(29) TF_RND(16) TF_RND(24)
    x0 += ks2; x1 += k0 + 2u;
    TF_RND(13) TF_RND(15) TF_RND(26) TF_RND(6)
    x0 += k0;  x1 += k1 + 3u;
    TF_RND(17) TF_RND(29) TF_RND(16) TF_RND(24)
    x0 += k1;  x1 += ks2 + 4u;
    TF_RND(13) TF_RND(15) TF_RND(26) TF_RND(6)
    x0 += ks2; x1 += k0 + 5u;
#undef TF_RND
    o0 = x0; o1 = x1;
}

// ===== software grid barrier (all NBLK blocks are co-resident) =====
__device__ __forceinline__ void grid_barrier() {
    __syncthreads();
    if (threadIdx.x == 0) {
        __threadfence();
        unsigned gen = g_bar_gen;
        if (atomicAdd(&g_bar_count, 1u) == NBLK - 1) {
            atomicExch(&g_bar_count, 0u);
            __threadfence();
            g_bar_gen = gen + 1u;
        } else {
            while (g_bar_gen == gen) __nanosleep(32);
        }
        __threadfence();
    }
    __syncthreads();
}

// ===== 64x64x512 GEMM tile: C[m0:m0+64, n0:n0+64] = A @ W^T + bias =====
// arow/wrow: per-thread row base pointers already offset by +lk.
__device__ __forceinline__ void gemm64(const float* __restrict__ arow,
                                       const float* __restrict__ wrow,
                                       const float* __restrict__ bias,
                                       float* __restrict__ C,
                                       int m0, int n0, int ldc,
                                       float* sA, float* sB) {
    const int tid = threadIdx.x;
    const int lm = tid >> 2;
    const int lk = (tid & 3) * 2;
    const int ty = tid >> 4, tx = tid & 15;
    float acc[16];
    #pragma unroll
    for (int i = 0; i < 16; i++) acc[i] = 0.f;

    for (int k0 = 0; k0 < Hdim; k0 += 8) {
        float2 a2 = *reinterpret_cast<const float2*>(arow + k0);
        float2 b2 = *reinterpret_cast<const float2*>(wrow + k0);
        __syncthreads();
        sA[lk * 68 + lm] = a2.x; sA[(lk + 1) * 68 + lm] = a2.y;
        sB[lk * 68 + lm] = b2.x; sB[(lk + 1) * 68 + lm] = b2.y;
        __syncthreads();
        #pragma unroll
        for (int k = 0; k < 8; k++) {
            float4 av = *reinterpret_cast<const float4*>(sA + k * 68 + ty * 4);
            float4 bv = *reinterpret_cast<const float4*>(sB + k * 68 + tx * 4);
            acc[0]  = fmaf(av.x, bv.x, acc[0]);  acc[1]  = fmaf(av.x, bv.y, acc[1]);
            acc[2]  = fmaf(av.x, bv.z, acc[2]);  acc[3]  = fmaf(av.x, bv.w, acc[3]);
            acc[4]  = fmaf(av.y, bv.x, acc[4]);  acc[5]  = fmaf(av.y, bv.y, acc[5]);
            acc[6]  = fmaf(av.y, bv.z, acc[6]);  acc[7]  = fmaf(av.y, bv.w, acc[7]);
            acc[8]  = fmaf(av.z, bv.x, acc[8]);  acc[9]  = fmaf(av.z, bv.y, acc[9]);
            acc[10] = fmaf(av.z, bv.z, acc[10]); acc[11] = fmaf(av.z, bv.w, acc[11]);
            acc[12] = fmaf(av.w, bv.x, acc[12]); acc[13] = fmaf(av.w, bv.y, acc[13]);
            acc[14] = fmaf(av.w, bv.z, acc[14]); acc[15] = fmaf(av.w, bv.w, acc[15]);
        }
    }
    __syncthreads();
    float4 bb = *reinterpret_cast<const float4*>(bias + n0 + tx * 4);
    #pragma unroll
    for (int i = 0; i < 4; i++) {
        int m = m0 + ty * 4 + i;
        float4 o;
        o.x = acc[i * 4 + 0] + bb.x;
        o.y = acc[i * 4 + 1] + bb.y;
        o.z = acc[i * 4 + 2] + bb.z;
        o.w = acc[i * 4 + 3] + bb.w;
        *reinterpret_cast<float4*>(&C[(size_t)m * ldc + n0 + tx * 4]) = o;
    }
}

// ===== main persistent kernel =====
__global__ void __launch_bounds__(NTHR, 1)
prior_persistent(const float* __restrict__ note, const float* __restrict__ genre,
                 const float* __restrict__ Whid, const float* __restrict__ bhid,
                 const float* __restrict__ emb,
                 const float* __restrict__ Wih1, const float* __restrict__ Whh1,
                 const float* __restrict__ bih1, const float* __restrict__ bhh1,
                 const float* __restrict__ Wih2, const float* __restrict__ Whh2,
                 const float* __restrict__ bih2, const float* __restrict__ bhh2,
                 const float* __restrict__ Wout, const float* __restrict__ bout,
                 float* __restrict__ out, float* __restrict__ tokout) {
    __shared__ __align__(16) float sA[8 * 68];
    __shared__ __align__(16) float sB[8 * 68];
    __shared__ float s_red[8];
    __shared__ float s_val[8];
    __shared__ int   s_idx[8];

    const int tid = threadIdx.x;
    const int bx = blockIdx.x;
    const int lm = tid >> 2;
    const int lk = (tid & 3) * 2;

    // ---------- init: sample keys, tok=0, h1 = concat(note,genre) @ Whid^T + bhid ----------
    {
        int gidx = bx * NTHR + tid;
        if (gidx < Tdim) {
            unsigned o0, o1;
            threefry2x32(0u, 42u, 0u, (unsigned)gidx, o0, o1);
            g_key0[gidx] = o0; g_key1[gidx] = o1;
        }
        if (gidx < Bdim) g_tok[gidx] = 0;

        for (int r = 0; r < Bdim / NBLK; r++) {      // 4 rows per block
            int b = bx * (Bdim / NBLK) + r;
            for (int i = tid; i < SKELdim; i += NTHR) sA[i] = note[b * SKELdim + i];
            for (int i = tid; i < GENdim; i += NTHR) sA[SKELdim + i] = genre[b * GENdim + i];
            __syncthreads();
            for (int j = tid; j < Hdim; j += NTHR) {
                const float* w = Whid + (size_t)j * (SKELdim + GENdim);
                float acc = 0.f;
                #pragma unroll 8
                for (int k = 0; k < SKELdim + GENdim; k++) acc = fmaf(sA[k], w[k], acc);
                g_h1[(size_t)b * Hdim + j] = acc + bhid[j];
            }
            __syncthreads();
        }
    }
    grid_barrier();

    for (int t = 0; t < Tdim; t++) {
        // ---------- GRU1 dual GEMM: gi = emb[tok] @ Wih1^T, gh = h1 @ Whh1^T ----------
        #pragma unroll 1
        for (int i = 0; i < 3; i++) {
            int tt = i * NBLK + bx;          // 0..383
            int z = tt / 192;                // 0: gi/Wih, 1: gh/Whh
            int r = tt - z * 192;
            int m0 = (r & 7) * 64, n0 = (r >> 3) * 64;
            const float* arow;
            if (z == 0) arow = emb + (size_t)g_tok[m0 + lm] * Hdim + lk;
            else        arow = g_h1 + (size_t)(m0 + lm) * Hdim + lk;
            const float* wrow = (z ? Whh1 : Wih1) + (size_t)(n0 + lm) * Hdim + lk;
            gemm64(arow, wrow, z ? bhh1 : bih1, z ? g_gh : g_gi, m0, n0, H3dim, sA, sB);
        }
        grid_barrier();

        // ---------- combine1 -> h1 ----------
        {
            int base = bx * (Bdim * Hdim / NBLK);
            #pragma unroll 1
            for (int j = 0; j < (Bdim * Hdim / NBLK) / NTHR; j++) {
                int idx = base + j * NTHR + tid;
                int b = idx >> 9, h = idx & (Hdim - 1);
                const float* gib = g_gi + (size_t)b * H3dim;
                const float* ghb = g_gh + (size_t)b * H3dim;
                float ir = gib[h], iz = gib[Hdim + h], in_ = gib[2 * Hdim + h];
                float hr = ghb[h], hz = ghb[Hdim + h], hn = ghb[2 * Hdim + h];
                float rr = 1.f / (1.f + expf(-(ir + hr)));
                float zz = 1.f / (1.f + expf(-(iz + hz)));
                float nn = tanhf(in_ + rr * hn);
                float hp = g_h1[idx];
                g_h1[idx] = (1.f - zz) * nn + zz * hp;
            }
        }
        grid_barrier();

        // ---------- GRU2 dual GEMM: gi = h1 @ Wih2^T, gh = hprev @ Whh2^T ----------
        const float* hprev = (t == 0) ? g_h1 : g_h2;
        #pragma unroll 1
        for (int i = 0; i < 3; i++) {
            int tt = i * NBLK + bx;
            int z = tt / 192;
            int r = tt - z * 192;
            int m0 = (r & 7) * 64, n0 = (r >> 3) * 64;
            const float* abase = (z == 0) ? g_h1 : hprev;
            const float* arow = abase + (size_t)(m0 + lm) * Hdim + lk;
            const float* wrow = (z ? Whh2 : Wih2) + (size_t)(n0 + lm) * Hdim + lk;
            gemm64(arow, wrow, z ? bhh2 : bih2, z ? g_gh : g_gi, m0, n0, H3dim, sA, sB);
        }
        grid_barrier();

        // ---------- combine2 -> h2 ----------
        {
            int base = bx * (Bdim * Hdim / NBLK);
            #pragma unroll 1
            for (int j = 0; j < (Bdim * Hdim / NBLK) / NTHR; j++) {
                int idx = base + j * NTHR + tid;
                int b = idx >> 9, h = idx & (Hdim - 1);
                const float* gib = g_gi + (size_t)b * H3dim;
                const float* ghb = g_gh + (size_t)b * H3dim;
                float ir = gib[h], iz = gib[Hdim + h], in_ = gib[2 * Hdim + h];
                float hr = ghb[h], hz = ghb[Hdim + h], hn = ghb[2 * Hdim + h];
                float rr = 1.f / (1.f + expf(-(ir + hr)));
                float zz = 1.f / (1.f + expf(-(iz + hz)));
                float nn = tanhf(in_ + rr * hn);
                float hp = (t == 0) ? g_h1[idx] : g_h2[idx];
                g_h2[idx] = (1.f - zz) * nn + zz * hp;
            }
        }
        grid_barrier();

        // ---------- out GEMM (32x64 tile per block): logits -> out[b, t, :] ----------
        {
            int tm = bx >> 3, tn = bx & 7;
            int m0 = tm * 32, n0 = tn * 64;
            // A: 32 rows x 8 k, one float per thread
            int am = tid >> 3, ak = tid & 7;
            // B: 64 rows x 8 k, float2 per thread
            int bn = tid >> 2, bk = (tid & 3) * 2;
            const float* arow = g_h2 + (size_t)(m0 + am) * Hdim + ak;
            const float* wrow = Wout + (size_t)(n0 + bn) * Hdim + bk;
            const int ty = tid >> 4, tx = tid & 15;
            float acc[8];
            #pragma unroll
            for (int i = 0; i < 8; i++) acc[i] = 0.f;
            // reuse sA with stride 36 (alignment: 36*4=144 bytes, 16B multiple)
            for (int k0 = 0; k0 < Hdim; k0 += 8) {
                float a1 = arow[k0];
                float2 b2 = *reinterpret_cast<const float2*>(wrow + k0);
                __syncthreads();
                sA[ak * 36 + am] = a1;
                sB[bk * 68 + bn] = b2.x; sB[(bk + 1) * 68 + bn] = b2.y;
                __syncthreads();
                #pragma unroll
                for (int k = 0; k < 8; k++) {
                    float2 av = *reinterpret_cast<const float2*>(sA + k * 36 + ty * 2);
                    float4 bv = *reinterpret_cast<const float4*>(sB + k * 68 + tx * 4);
                    acc[0] = fmaf(av.x, bv.x, acc[0]); acc[1] = fmaf(av.x, bv.y, acc[1]);
                    acc[2] = fmaf(av.x, bv.z, acc[2]); acc[3] = fmaf(av.x, bv.w, acc[3]);
                    acc[4] = fmaf(av.y, bv.x, acc[4]); acc[5] = fmaf(av.y, bv.y, acc[5]);
                    acc[6] = fmaf(av.y, bv.z, acc[6]); acc[7] = fmaf(av.y, bv.w, acc[7]);
                }
            }
            __syncthreads();
            float4 bb = *reinterpret_cast<const float4*>(bout + n0 + tx * 4);
            #pragma unroll
            for (int i = 0; i < 2; i++) {
                int m = m0 + ty * 2 + i;
                float* orow = out + (size_t)m * Tdim * NCdim + (size_t)t * NCdim;
                float4 o;
                o.x = acc[i * 4 + 0] + bb.x;
                o.y = acc[i * 4 + 1] + bb.y;
                o.z = acc[i * 4 + 2] + bb.z;
                o.w = acc[i * 4 + 3] + bb.w;
                *reinterpret_cast<float4*>(&orow[n0 + tx * 4]) = o;
            }
        }
        grid_barrier();

        // ---------- sample: 4 rows per block ----------
        {
            unsigned key0 = g_key0[t], key1 = g_key1[t];
            const int lane = tid & 31, wrp = tid >> 5;
            #pragma unroll 1
            for (int i = 0; i < Bdim / NBLK; i++) {
                int b = bx + i * NBLK;
                const float* row = out + (size_t)b * Tdim * NCdim + (size_t)t * NCdim;

                // row max
                float mx = -3.402823466e38f;
                for (int c = tid; c < NCdim; c += NTHR) mx = fmaxf(mx, row[c]);
                #pragma unroll
                for (int o = 16; o; o >>= 1) mx = fmaxf(mx, __shfl_xor_sync(0xffffffffu, mx, o));
                if (lane == 0) s_red[wrp] = mx;
                __syncthreads();
                float m2 = s_red[0];
                #pragma unroll
                for (int k = 1; k < 8; k++) m2 = fmaxf(m2, s_red[k]);
                mx = m2;
                __syncthreads();

                // logsumexp
                float s = 0.f;
                for (int c = tid; c < NCdim; c += NTHR) s += expf(row[c] - mx);
                #pragma unroll
                for (int o = 16; o; o >>= 1) s += __shfl_xor_sync(0xffffffffu, s, o);
                if (lane == 0) s_red[wrp] = s;
                __syncthreads();
                float s2 = 0.f;
                #pragma unroll
                for (int k = 0; k < 8; k++) s2 += s_red[k];
                float lse = logf(s2);
                __syncthreads();

                // gumbel argmax, first-index tie break
                float best = -3.402823466e38f;
                int bi = NCdim;
                const float tiny = 1.17549435e-38f;
                for (int c = tid; c < NCdim; c += NTHR) {
                    unsigned j = (unsigned)(b * NCdim + c);
                    unsigned o0, o1;
                    threefry2x32(key0, key1, 0u, j, o0, o1);
#if BITS_FOLD_XOR
                    unsigned bits = o0 ^ o1;
#else
                    unsigned bits = o0;
#endif
                    float f = __uint_as_float((bits >> 9) | 0x3F800000u) - 1.0f;
                    float u = fmaxf(tiny, f + tiny);
                    float g = -logf(-logf(u));
                    float v = ((row[c] - mx) - lse) + g;
                    if (v > best) { best = v; bi = c; }
                }
                #pragma unroll
                for (int o = 16; o; o >>= 1) {
                    float ov = __shfl_xor_sync(0xffffffffu, best, o);
                    int   oi = __shfl_xor_sync(0xffffffffu, bi, o);
                    if (ov > best || (ov == best && oi < bi)) { best = ov; bi = oi; }
                }
                if (lane == 0) { s_val[wrp] = best; s_idx[wrp] = bi; }
                __syncthreads();
                if (tid == 0) {
                    float bv = s_val[0]; int bidx = s_idx[0];
                    #pragma unroll
                    for (int k = 1; k < 8; k++) {
                        if (s_val[k] > bv || (s_val[k] == bv && s_idx[k] < bidx)) {
                            bv = s_val[k]; bidx = s_idx[k];
                        }
                    }
                    g_tok[b] = bidx;
                    if (tokout) tokout[(size_t)b * Tdim + t] = (float)bidx;
                }
                __syncthreads();
            }
        }
        grid_barrier();
    }
}

// ===== launch: ONE graph node =====
extern "C" void kernel_launch(void* const* d_in, const int* in_sizes, int n_in,
                              void* d_out, int out_size) {
    const float* note  = (const float*)d_in[1];
    const float* genre = (const float*)d_in[2];
    const float* W_hid = (const float*)d_in[3];
    const float* b_hid = (const float*)d_in[4];
    const float* emb   = (const float*)d_in[5];
    const float* W_ih1 = (const float*)d_in[6];
    const float* W_hh1 = (const float*)d_in[7];
    const float* b_ih1 = (const float*)d_in[8];
    const float* b_hh1 = (const float*)d_in[9];
    const float* W_ih2 = (const float*)d_in[10];
    const float* W_hh2 = (const float*)d_in[11];
    const float* b_ih2 = (const float*)d_in[12];
    const float* b_hh2 = (const float*)d_in[13];
    const float* W_out = (const float*)d_in[14];
    const float* b_out = (const float*)d_in[15];

    float* out = (float*)d_out;
    const long long need = (long long)Bdim * Tdim * NCdim + (long long)Bdim * Tdim;
    float* tokout = ((long long)out_size >= need) ? (out + (size_t)Bdim * Tdim * NCdim) : nullptr;

    prior_persistent<<<NBLK, NTHR>>>(note, genre, W_hid, b_hid, emb,
                                     W_ih1, W_hh1, b_ih1, b_hh1,
                                     W_ih2, W_hh2, b_ih2, b_hh2,
                                     W_out, b_out, out, tokout);
}

// round 4
// speedup vs baseline: 1.0449x; 1.0449x over previous
#include <cuda_runtime.h>
#include <stdint.h>
#include <math.h>

// ===== problem dims =====
#define Bdim 512
#define Tdim 256
#define Hdim 512
#define NCdim 512
#define SKELdim 256
#define GENdim 16

#define NBLK 128
#define NTHR 256

typedef unsigned long long ull;

// dynamic smem layout (floats):
//  sAe: [2][8*36]   = 576
//  sAh: [2][8*36]   = 576
//  sBi: [2][8*384]  = 6144   (duplicated-pair B for Wih)
//  sBh: [2][8*384]  = 6144   (duplicated-pair B for Whh)
#define SMEM_FLOATS (576 + 576 + 6144 + 6144)
#define SMEM_BYTES  (SMEM_FLOATS * 4)

// ===== persistent device state =====
__device__ float g_h1a[Bdim * Hdim];
__device__ float g_h1b[Bdim * Hdim];
__device__ float g_h2a[Bdim * Hdim];
__device__ float g_h2b[Bdim * Hdim];
__device__ int   g_tok[Bdim];
__device__ unsigned g_key0[Tdim];
__device__ unsigned g_key1[Tdim];
__device__ unsigned g_bar_count;
__device__ volatile unsigned g_bar_gen;

// ===== packed f32x2 fma =====
__device__ __forceinline__ void fma2(ull& d, ull a, ull b) {
    asm("fma.rn.f32x2 %0, %1, %2, %0;" : "+l"(d) : "l"(a), "l"(b));
}
__device__ __forceinline__ float pick(ull v, int mm) {
    return __uint_as_float(mm ? (unsigned)(v >> 32) : (unsigned)(v & 0xffffffffull));
}

// ===== threefry2x32 =====
__device__ __forceinline__ void threefry2x32(unsigned k0, unsigned k1,
                                             unsigned c0, unsigned c1,
                                             unsigned& o0, unsigned& o1) {
    unsigned ks2 = k0 ^ k1 ^ 0x1BD11BDAu;
    unsigned x0 = c0 + k0;
    unsigned x1 = c1 + k1;
#define TF_RND(r) { x0 += x1; x1 = (x1 << (r)) | (x1 >> (32 - (r))); x1 ^= x0; }
    TF_RND(13) TF_RND(15) TF_RND(26) TF_RND(6)
    x0 += k1;  x1 += ks2 + 1u;
    TF_RND(17) TF_RND(29) TF_RND(16) TF_RND(24)
    x0 += ks2; x1 += k0 + 2u;
    TF_RND(13) TF_RND(15) TF_RND(26) TF_RND(6)
    x0 += k0;  x1 += k1 + 3u;
    TF_RND(17) TF_RND(29) TF_RND(16) TF_RND(24)
    x0 += k1;  x1 += ks2 + 4u;
    TF_RND(13) TF_RND(15) TF_RND(26) TF_RND(6)
    x0 += ks2; x1 += k0 + 5u;
#undef TF_RND
    o0 = x0; o1 = x1;
}

// ===== software grid barrier =====
__device__ __forceinline__ void grid_barrier() {
    __syncthreads();
    if (threadIdx.x == 0) {
        __threadfence();
        unsigned gen = g_bar_gen;
        if (atomicAdd(&g_bar_count, 1u) == NBLK - 1) {
            atomicExch(&g_bar_count, 0u);
            __threadfence();
            g_bar_gen = gen + 1u;
        } else {
            while (g_bar_gen == gen) __nanosleep(32);
        }
        __threadfence();
    }
    __syncthreads();
}

__device__ __forceinline__ void loadf8(float* r, const float* p) {
    float4 v0 = *reinterpret_cast<const float4*>(p);
    float4 v1 = *reinterpret_cast<const float4*>(p + 4);
    r[0] = v0.x; r[1] = v0.y; r[2] = v0.z; r[3] = v0.w;
    r[4] = v1.x; r[5] = v1.y; r[6] = v1.z; r[7] = v1.w;
}

// ===== fused GRU stage: dual GEMM (gi = X@Wih^T, gh = Hin@Whh^T) + combine =====
// Tile: 32 m-rows x 64 h (x3 gates = 192 cols, gate-interleaved: col = h_local*3 + gate).
// micro: warp ty (4 m-rows, as 2 f32x2 m-pairs) x lane tx (6 cols, 2 h x 3 gates).
template<bool EMB>
__device__ void gru_stage(const float* __restrict__ X,
                          const float* __restrict__ Hin,
                          const float* __restrict__ Wih, const float* __restrict__ Whh,
                          const float* __restrict__ bih, const float* __restrict__ bhh,
                          const float* __restrict__ Hblend,
                          float* __restrict__ Hout,
                          float* smem) {
    const int tid = threadIdx.x, bx = blockIdx.x;
    const int m0 = (bx >> 3) * 32;
    const int h0 = (bx & 7) * 64;
    float* sAe = smem;
    float* sAh = smem + 576;
    float* sBi = smem + 1152;
    float* sBh = smem + 1152 + 6144;

    const float* gxi = nullptr;
    const float* gxh = nullptr;
    const float* ax  = nullptr;
    int arow = 0;
    const bool isA = (tid >= 192);
    if (!isA) {
        int c = tid;
        int g = c % 3, hl = c / 3;
        size_t wr = (size_t)(g * Hdim + h0 + hl) * Hdim;
        gxi = Wih + wr;
        gxh = Whh + wr;
    } else {
        int u = tid - 192;
        if (u < 32) {
            arow = u;
            if (EMB) ax = X + (size_t)g_tok[m0 + u] * Hdim;
            else     ax = X + (size_t)(m0 + u) * Hdim;
        } else {
            arow = u - 32;
            ax = Hin + (size_t)(m0 + arow) * Hdim;
        }
    }

    ull a0[2][6], a1[2][6];
    #pragma unroll
    for (int p = 0; p < 2; p++)
        #pragma unroll
        for (int j = 0; j < 6; j++) { a0[p][j] = 0ull; a1[p][j] = 0ull; }

    float pwi[8], pwh[8], pa[8];
    // prologue: load + store chunk 0 -> buf 0
    if (!isA) { loadf8(pwi, gxi); loadf8(pwh, gxh); }
    else      { loadf8(pa, ax); }
    if (!isA) {
        int c2 = tid * 2;
        #pragma unroll
        for (int k = 0; k < 8; k++) {
            *reinterpret_cast<float2*>(sBi + k * 384 + c2) = make_float2(pwi[k], pwi[k]);
            *reinterpret_cast<float2*>(sBh + k * 384 + c2) = make_float2(pwh[k], pwh[k]);
        }
    } else {
        float* dst = (tid < 224) ? sAe : sAh;
        #pragma unroll
        for (int k = 0; k < 8; k++) dst[k * 36 + arow] = pa[k];
    }
    __syncthreads();

    const int ty4 = (tid >> 5) << 2;
    const int txo = (tid & 31) * 12;

    #pragma unroll 2
    for (int k0 = 0; k0 < Hdim; k0 += 8) {
        const int buf = (k0 >> 3) & 1;
        const bool more = (k0 + 8) < Hdim;
        if (more) {
            if (!isA) { loadf8(pwi, gxi + k0 + 8); loadf8(pwh, gxh + k0 + 8); }
            else      { loadf8(pa, ax + k0 + 8); }
        }
        #pragma unroll
        for (int k = 0; k < 8; k++) {
            ulonglong2 ae = *reinterpret_cast<const ulonglong2*>(sAe + buf * 288 + k * 36 + ty4);
            ulonglong2 ah = *reinterpret_cast<const ulonglong2*>(sAh + buf * 288 + k * 36 + ty4);
            const float* bp = sBi + buf * 3072 + k * 384 + txo;
            ulonglong2 b0 = *reinterpret_cast<const ulonglong2*>(bp);
            ulonglong2 b1 = *reinterpret_cast<const ulonglong2*>(bp + 4);
            ulonglong2 b2 = *reinterpret_cast<const ulonglong2*>(bp + 8);
            fma2(a0[0][0], ae.x, b0.x); fma2(a0[0][1], ae.x, b0.y);
            fma2(a0[0][2], ae.x, b1.x); fma2(a0[0][3], ae.x, b1.y);
            fma2(a0[0][4], ae.x, b2.x); fma2(a0[0][5], ae.x, b2.y);
            fma2(a0[1][0], ae.y, b0.x); fma2(a0[1][1], ae.y, b0.y);
            fma2(a0[1][2], ae.y, b1.x); fma2(a0[1][3], ae.y, b1.y);
            fma2(a0[1][4], ae.y, b2.x); fma2(a0[1][5], ae.y, b2.y);
            const float* cp = sBh + buf * 3072 + k * 384 + txo;
            ulonglong2 c0 = *reinterpret_cast<const ulonglong2*>(cp);
            ulonglong2 c1 = *reinterpret_cast<const ulonglong2*>(cp + 4);
            ulonglong2 c2 = *reinterpret_cast<const ulonglong2*>(cp + 8);
            fma2(a1[0][0], ah.x, c0.x); fma2(a1[0][1], ah.x, c0.y);
            fma2(a1[0][2], ah.x, c1.x); fma2(a1[0][3], ah.x, c1.y);
            fma2(a1[0][4], ah.x, c2.x); fma2(a1[0][5], ah.x, c2.y);
            fma2(a1[1][0], ah.y, c0.x); fma2(a1[1][1], ah.y, c0.y);
            fma2(a1[1][2], ah.y, c1.x); fma2(a1[1][3], ah.y, c1.y);
            fma2(a1[1][4], ah.y, c2.x); fma2(a1[1][5], ah.y, c2.y);
        }
        if (more) {
            const int nb = buf ^ 1;
            if (!isA) {
                int c2w = tid * 2;
                #pragma unroll
                for (int k = 0; k < 8; k++) {
                    *reinterpret_cast<float2*>(sBi + nb * 3072 + k * 384 + c2w) = make_float2(pwi[k], pwi[k]);
                    *reinterpret_cast<float2*>(sBh + nb * 3072 + k * 384 + c2w) = make_float2(pwh[k], pwh[k]);
                }
            } else {
                float* dst = ((tid < 224) ? sAe : sAh) + nb * 288;
                #pragma unroll
                for (int k = 0; k < 8; k++) dst[k * 36 + arow] = pa[k];
            }
        }
        __syncthreads();
    }

    // epilogue: gate combine in registers, write Hout tile
    const int txh = (tid & 31) * 2;
    const int hA = h0 + txh;
    float bir[2], biz[2], bin_[2], bhr[2], bhz[2], bhn[2];
    #pragma unroll
    for (int hh = 0; hh < 2; hh++) {
        bir[hh]  = bih[hA + hh];
        biz[hh]  = bih[Hdim + hA + hh];
        bin_[hh] = bih[2 * Hdim + hA + hh];
        bhr[hh]  = bhh[hA + hh];
        bhz[hh]  = bhh[Hdim + hA + hh];
        bhn[hh]  = bhh[2 * Hdim + hA + hh];
    }
    #pragma unroll
    for (int p = 0; p < 2; p++) {
        #pragma unroll
        for (int mm = 0; mm < 2; mm++) {
            int m = m0 + ty4 + p * 2 + mm;
            float2 hp = *reinterpret_cast<const float2*>(Hblend + (size_t)m * Hdim + hA);
            float o[2];
            #pragma unroll
            for (int hh = 0; hh < 2; hh++) {
                float ir  = pick(a0[p][hh * 3 + 0], mm) + bir[hh];
                float iz  = pick(a0[p][hh * 3 + 1], mm) + biz[hh];
                float in_ = pick(a0[p][hh * 3 + 2], mm) + bin_[hh];
                float hr  = pick(a1[p][hh * 3 + 0], mm) + bhr[hh];
                float hz  = pick(a1[p][hh * 3 + 1], mm) + bhz[hh];
                float hn  = pick(a1[p][hh * 3 + 2], mm) + bhn[hh];
                float r = 1.f / (1.f + expf(-(ir + hr)));
                float z = 1.f / (1.f + expf(-(iz + hz)));
                float n = tanhf(in_ + r * hn);
                float hprev = hh ? hp.y : hp.x;
                o[hh] = (1.f - z) * n + z * hprev;
            }
            *reinterpret_cast<float2*>(Hout + (size_t)m * Hdim + hA) = make_float2(o[0], o[1]);
        }
    }
}

// ===== out GEMM: 32x64 tile, logits -> out[b, t, :] =====
__device__ void out_stage(const float* __restrict__ H2, const float* __restrict__ Wout,
                          const float* __restrict__ bout, float* __restrict__ out,
                          int t, float* smem) {
    const int tid = threadIdx.x, bx = blockIdx.x;
    const int m0 = (bx >> 3) * 32;
    const int n0 = (bx & 7) * 64;
    float* sA = smem;          // [2][8*36]
    float* sB = smem + 576;    // [2][8*128] duplicated-pair

    const int role = (tid < 64) ? 0 : (tid < 96 ? 1 : 2);
    const float* wrow = nullptr;
    const float* arp  = nullptr;
    int arow = 0;
    if (role == 0) wrow = Wout + (size_t)(n0 + tid) * Hdim;
    else if (role == 1) { arow = tid - 64; arp = H2 + (size_t)(m0 + arow) * Hdim; }

    ull acc[2][2];
    acc[0][0] = acc[0][1] = acc[1][0] = acc[1][1] = 0ull;

    float pw[8], pa[8];
    if (role == 0) loadf8(pw, wrow);
    else if (role == 1) loadf8(pa, arp);
    if (role == 0) {
        int c2 = tid * 2;
        #pragma unroll
        for (int k = 0; k < 8; k++)
            *reinterpret_cast<float2*>(sB + k * 128 + c2) = make_float2(pw[k], pw[k]);
    } else if (role == 1) {
        #pragma unroll
        for (int k = 0; k < 8; k++) sA[k * 36 + arow] = pa[k];
    }
    __syncthreads();

    const int ty4 = (tid >> 5) << 2;
    const int txo = (tid & 31) * 4;

    #pragma unroll 2
    for (int k0 = 0; k0 < Hdim; k0 += 8) {
        const int buf = (k0 >> 3) & 1;
        const bool more = (k0 + 8) < Hdim;
        if (more) {
            if (role == 0) loadf8(pw, wrow + k0 + 8);
            else if (role == 1) loadf8(pa, arp + k0 + 8);
        }
        #pragma unroll
        for (int k = 0; k < 8; k++) {
            ulonglong2 av = *reinterpret_cast<const ulonglong2*>(sA + buf * 288 + k * 36 + ty4);
            ulonglong2 bv = *reinterpret_cast<const ulonglong2*>(sB + buf * 1024 + k * 128 + txo);
            fma2(acc[0][0], av.x, bv.x); fma2(acc[0][1], av.x, bv.y);
            fma2(acc[1][0], av.y, bv.x); fma2(acc[1][1], av.y, bv.y);
        }
        if (more) {
            const int nb = buf ^ 1;
            if (role == 0) {
                int c2 = tid * 2;
                #pragma unroll
                for (int k = 0; k < 8; k++)
                    *reinterpret_cast<float2*>(sB + nb * 1024 + k * 128 + c2) = make_float2(pw[k], pw[k]);
            } else if (role == 1) {
                #pragma unroll
                for (int k = 0; k < 8; k++) sA[nb * 288 + k * 36 + arow] = pa[k];
            }
        }
        __syncthreads();
    }

    const int nn = n0 + (tid & 31) * 2;
    float bb0 = bout[nn], bb1 = bout[nn + 1];
    #pragma unroll
    for (int p = 0; p < 2; p++) {
        #pragma unroll
        for (int mm = 0; mm < 2; mm++) {
            int m = m0 + ty4 + p * 2 + mm;
            float2 o = make_float2(pick(acc[p][0], mm) + bb0, pick(acc[p][1], mm) + bb1);
            *reinterpret_cast<float2*>(out + (size_t)m * (Tdim * NCdim) + (size_t)t * NCdim + nn) = o;
        }
    }
}

// ===== sample stage: 4 rows per block =====
__device__ void sample_stage(const float* __restrict__ out, float* __restrict__ tokout, int t) {
    __shared__ float s_red[8];
    __shared__ float s_val[8];
    __shared__ int   s_idx[8];
    const int tid = threadIdx.x, bx = blockIdx.x;
    const int lane = tid & 31, wrp = tid >> 5;
    unsigned key0 = g_key0[t], key1 = g_key1[t];
    #pragma unroll 1
    for (int i = 0; i < Bdim / NBLK; i++) {
        int b = bx + i * NBLK;
        const float* row = out + (size_t)b * Tdim * NCdim + (size_t)t * NCdim;

        float mx = -3.402823466e38f;
        for (int c = tid; c < NCdim; c += NTHR) mx = fmaxf(mx, row[c]);
        #pragma unroll
        for (int o = 16; o; o >>= 1) mx = fmaxf(mx, __shfl_xor_sync(0xffffffffu, mx, o));
        if (lane == 0) s_red[wrp] = mx;
        __syncthreads();
        float m2 = s_red[0];
        #pragma unroll
        for (int k = 1; k < 8; k++) m2 = fmaxf(m2, s_red[k]);
        mx = m2;
        __syncthreads();

        float s = 0.f;
        for (int c = tid; c < NCdim; c += NTHR) s += expf(row[c] - mx);
        #pragma unroll
        for (int o = 16; o; o >>= 1) s += __shfl_xor_sync(0xffffffffu, s, o);
        if (lane == 0) s_red[wrp] = s;
        __syncthreads();
        float s2 = 0.f;
        #pragma unroll
        for (int k = 0; k < 8; k++) s2 += s_red[k];
        float lse = logf(s2);
        __syncthreads();

        float best = -3.402823466e38f;
        int bi = NCdim;
        const float tiny = 1.17549435e-38f;
        for (int c = tid; c < NCdim; c += NTHR) {
            unsigned j = (unsigned)(b * NCdim + c);
            unsigned o0, o1;
            threefry2x32(key0, key1, 0u, j, o0, o1);
            unsigned bits = o0 ^ o1;
            float f = __uint_as_float((bits >> 9) | 0x3F800000u) - 1.0f;
            float u = fmaxf(tiny, f + tiny);
            float g = -logf(-logf(u));
            float v = ((row[c] - mx) - lse) + g;
            if (v > best) { best = v; bi = c; }
        }
        #pragma unroll
        for (int o = 16; o; o >>= 1) {
            float ov = __shfl_xor_sync(0xffffffffu, best, o);
            int   oi = __shfl_xor_sync(0xffffffffu, bi, o);
            if (ov > best || (ov == best && oi < bi)) { best = ov; bi = oi; }
        }
        if (lane == 0) { s_val[wrp] = best; s_idx[wrp] = bi; }
        __syncthreads();
        if (tid == 0) {
            float bv = s_val[0]; int bidx = s_idx[0];
            #pragma unroll
            for (int k = 1; k < 8; k++) {
                if (s_val[k] > bv || (s_val[k] == bv && s_idx[k] < bidx)) {
                    bv = s_val[k]; bidx = s_idx[k];
                }
            }
            g_tok[b] = bidx;
            if (tokout) tokout[(size_t)b * Tdim + t] = (float)bidx;
        }
        __syncthreads();
    }
}

// ===== main persistent kernel =====
__global__ void __launch_bounds__(NTHR, 1)
prior_persistent(const float* __restrict__ note, const float* __restrict__ genre,
                 const float* __restrict__ Whid, const float* __restrict__ bhid,
                 const float* __restrict__ emb,
                 const float* __restrict__ Wih1, const float* __restrict__ Whh1,
                 const float* __restrict__ bih1, const float* __restrict__ bhh1,
                 const float* __restrict__ Wih2, const float* __restrict__ Whh2,
                 const float* __restrict__ bih2, const float* __restrict__ bhh2,
                 const float* __restrict__ Wout, const float* __restrict__ bout,
                 float* __restrict__ out, float* __restrict__ tokout) {
    extern __shared__ float smem[];
    const int tid = threadIdx.x, bx = blockIdx.x;

    // ---------- init ----------
    {
        int gidx = bx * NTHR + tid;
        if (gidx < Tdim) {
            unsigned o0, o1;
            threefry2x32(0u, 42u, 0u, (unsigned)gidx, o0, o1);
            g_key0[gidx] = o0; g_key1[gidx] = o1;
        }
        if (gidx < Bdim) g_tok[gidx] = 0;

        for (int r = 0; r < Bdim / NBLK; r++) {
            int b = bx * (Bdim / NBLK) + r;
            for (int i = tid; i < SKELdim; i += NTHR) smem[i] = note[b * SKELdim + i];
            for (int i = tid; i < GENdim; i += NTHR) smem[SKELdim + i] = genre[b * GENdim + i];
            __syncthreads();
            for (int j = tid; j < Hdim; j += NTHR) {
                const float* w = Whid + (size_t)j * (SKELdim + GENdim);
                float acc = 0.f;
                #pragma unroll 8
                for (int k = 0; k < SKELdim + GENdim; k++) acc = fmaf(smem[k], w[k], acc);
                g_h1a[(size_t)b * Hdim + j] = acc + bhid[j];
            }
            __syncthreads();
        }
    }
    grid_barrier();

    for (int t = 0; t < Tdim; t++) {
        const float* h1r; float* h1w; const float* h2r; float* h2w;
        if (t & 1) { h1r = g_h1b; h1w = g_h1a; h2r = g_h2b; h2w = g_h2a; }
        else       { h1r = g_h1a; h1w = g_h1b; h2r = g_h2a; h2w = g_h2b; }

        gru_stage<true>(emb, h1r, Wih1, Whh1, bih1, bhh1, h1r, h1w, smem);
        grid_barrier();

        const float* hp2 = (t == 0) ? (const float*)h1w : h2r;
        gru_stage<false>(h1w, hp2, Wih2, Whh2, bih2, bhh2, hp2, h2w, smem);
        grid_barrier();

        out_stage(h2w, Wout, bout, out, t, smem);
        grid_barrier();

        sample_stage(out, tokout, t);
        grid_barrier();
    }
}

// ===== launch: ONE graph node =====
extern "C" void kernel_launch(void* const* d_in, const int* in_sizes, int n_in,
                              void* d_out, int out_size) {
    const float* note  = (const float*)d_in[1];
    const float* genre = (const float*)d_in[2];
    const float* W_hid = (const float*)d_in[3];
    const float* b_hid = (const float*)d_in[4];
    const float* emb   = (const float*)d_in[5];
    const float* W_ih1 = (const float*)d_in[6];
    const float* W_hh1 = (const float*)d_in[7];
    const float* b_ih1 = (const float*)d_in[8];
    const float* b_hh1 = (const float*)d_in[9];
    const float* W_ih2 = (const float*)d_in[10];
    const float* W_hh2 = (const float*)d_in[11];
    const float* b_ih2 = (const float*)d_in[12];
    const float* b_hh2 = (const float*)d_in[13];
    const float* W_out = (const float*)d_in[14];
    const float* b_out = (const float*)d_in[15];

    float* out = (float*)d_out;
    const long long need = (long long)Bdim * Tdim * NCdim + (long long)Bdim * Tdim;
    float* tokout = ((long long)out_size >= need) ? (out + (size_t)Bdim * Tdim * NCdim) : nullptr;

    cudaFuncSetAttribute(prior_persistent,
                         cudaFuncAttributeMaxDynamicSharedMemorySize, SMEM_BYTES);

    prior_persistent<<<NBLK, NTHR, SMEM_BYTES>>>(note, genre, W_hid, b_hid, emb,
                                                 W_ih1, W_hh1, b_ih1, b_hh1,
                                                 W_ih2, W_hh2, b_ih2, b_hh2,
                                                 W_out, b_out, out, tokout);
}

// round 6
// speedup vs baseline: 1.0738x; 1.0277x over previous
#include <cuda_runtime.h>
#include <stdint.h>
#include <math.h>

// ===== problem dims =====
#define Bdim 512
#define Tdim 256
#define Hdim 512
#define NCdim 512
#define SKELdim 256
#define GENdim 16

#define NBLK 128
#define NTHR 256

typedef unsigned long long ull;

// dynamic smem (floats):
// GRU stage:  sAe [2][8][32]=512 | sAh 512 | sBi [2][8][192]=3072 | sBh 3072  -> 7168
// OUT stage:  sA  [2][8][4]=64   | sB  [2][8][512]=8192 | sL 4*512=2048      -> 10304
#define SMEM_FLOATS 10304
#define SMEM_BYTES  (SMEM_FLOATS * 4)

// ===== persistent device state =====
__device__ float g_h1a[Bdim * Hdim];
__device__ float g_h1b[Bdim * Hdim];
__device__ float g_h2a[Bdim * Hdim];
__device__ float g_h2b[Bdim * Hdim];
__device__ int   g_tok[Bdim];
__device__ unsigned g_key0[Tdim];
__device__ unsigned g_key1[Tdim];
__device__ unsigned g_bar_count;
__device__ volatile unsigned g_bar_gen;

// ===== packed f32x2 helpers =====
__device__ __forceinline__ void fma2(ull& d, ull a, ull b) {
    asm("fma.rn.f32x2 %0, %1, %2, %0;" : "+l"(d) : "l"(a), "l"(b));
}
__device__ __forceinline__ ull dup2(float b) {
    ull r; asm("mov.b64 %0, {%1, %1};" : "=l"(r) : "f"(b)); return r;
}
__device__ __forceinline__ float pick(ull v, int mm) {
    return __uint_as_float(mm ? (unsigned)(v >> 32) : (unsigned)(v & 0xffffffffull));
}

// ===== threefry2x32 =====
__device__ __forceinline__ void threefry2x32(unsigned k0, unsigned k1,
                                             unsigned c0, unsigned c1,
                                             unsigned& o0, unsigned& o1) {
    unsigned ks2 = k0 ^ k1 ^ 0x1BD11BDAu;
    unsigned x0 = c0 + k0;
    unsigned x1 = c1 + k1;
#define TF_RND(r) { x0 += x1; x1 = (x1 << (r)) | (x1 >> (32 - (r))); x1 ^= x0; }
    TF_RND(13) TF_RND(15) TF_RND(26) TF_RND(6)
    x0 += k1;  x1 += ks2 + 1u;
    TF_RND(17) TF_RND(29) TF_RND(16) TF_RND(24)
    x0 += ks2; x1 += k0 + 2u;
    TF_RND(13) TF_RND(15) TF_RND(26) TF_RND(6)
    x0 += k0;  x1 += k1 + 3u;
    TF_RND(17) TF_RND(29) TF_RND(16) TF_RND(24)
    x0 += k1;  x1 += ks2 + 4u;
    TF_RND(13) TF_RND(15) TF_RND(26) TF_RND(6)
    x0 += ks2; x1 += k0 + 5u;
#undef TF_RND
    o0 = x0; o1 = x1;
}

// ===== software grid barrier =====
__device__ __forceinline__ void grid_barrier() {
    __syncthreads();
    if (threadIdx.x == 0) {
        __threadfence();
        unsigned gen = g_bar_gen;
        if (atomicAdd(&g_bar_count, 1u) == NBLK - 1) {
            atomicExch(&g_bar_count, 0u);
            __threadfence();
            g_bar_gen = gen + 1u;
        } else {
            while (g_bar_gen == gen) __nanosleep(32);
        }
        __threadfence();
    }
    __syncthreads();
}

__device__ __forceinline__ void loadf8(float* r, const float* p) {
    float4 v0 = *reinterpret_cast<const float4*>(p);
    float4 v1 = *reinterpret_cast<const float4*>(p + 4);
    r[0] = v0.x; r[1] = v0.y; r[2] = v0.z; r[3] = v0.w;
    r[4] = v1.x; r[5] = v1.y; r[6] = v1.z; r[7] = v1.w;
}

// ===== fused GRU stage =====
// Block tile: 32 m-rows x 64 h (x3 gates, gate-major col = gate*64 + hl) for BOTH gemms.
// Warps: 4 m-parts (8 rows = 4 f32x2 m-pairs) x 2 h-parts (32 h per lane-set).
// A natural in smem (m-pairs, 128B warp loads). B scalar in smem, dup'd in reg.
template<bool EMB>
__device__ void gru_stage(const float* __restrict__ X,
                          const float* __restrict__ Hin,
                          const float* __restrict__ Wih, const float* __restrict__ Whh,
                          const float* __restrict__ bih, const float* __restrict__ bhh,
                          float* __restrict__ Hout,
                          float* smem) {
    const int tid = threadIdx.x, bx = blockIdx.x;
    const int m0 = (bx >> 3) * 32;
    const int h0 = (bx & 7) * 64;
    float* sAe = smem;              // [2][8][32]
    float* sAh = smem + 512;        // [2][8][32]
    float* sBi = smem + 1024;       // [2][8][192]
    float* sBh = smem + 4096;       // [2][8][192]

    const int warp = tid >> 5, lane = tid & 31;
    const int mpart = warp >> 1, hpart = warp & 1;
    const int hl = hpart * 32 + lane;          // 0..63
    const int h  = h0 + hl;

    // loader roles
    const bool isB = (tid < 192);
    const float* gbi = nullptr;
    const float* gbh = nullptr;
    const float* gax = nullptr;
    float* aDst = nullptr;
    int arow = 0;
    if (isB) {
        // col c = tid = gate*64 + hl2  -> W row = gate*Hdim + h0 + hl2
        int g = tid >> 6, hl2 = tid & 63;
        size_t wr = (size_t)(g * Hdim + h0 + hl2) * Hdim;
        gbi = Wih + wr;
        gbh = Whh + wr;
    } else {
        int u = tid - 192;
        if (u < 32) {
            arow = u;
            if (EMB) gax = X + (size_t)g_tok[m0 + u] * Hdim;
            else     gax = X + (size_t)(m0 + u) * Hdim;
            aDst = sAe;
        } else {
            arow = u - 32;
            gax = Hin + (size_t)(m0 + arow) * Hdim;
            aDst = sAh;
        }
    }

    ull accI[12], accH[12];   // [mp*3 + g]
    #pragma unroll
    for (int i = 0; i < 12; i++) { accI[i] = 0ull; accH[i] = 0ull; }

    float pwi[8], pwh[8], pa[8];
    // prologue: chunk 0 -> buf 0
    if (isB) { loadf8(pwi, gbi); loadf8(pwh, gbh); }
    else     { loadf8(pa, gax); }
    if (isB) {
        #pragma unroll
        for (int k = 0; k < 8; k++) {
            sBi[k * 192 + tid] = pwi[k];
            sBh[k * 192 + tid] = pwh[k];
        }
    } else {
        #pragma unroll
        for (int k = 0; k < 8; k++) aDst[k * 32 + arow] = pa[k];
    }
    __syncthreads();

    const int aoff = mpart * 8;   // float offset of this warp's 8 m-rows

    #pragma unroll 1
    for (int k0 = 0; k0 < Hdim; k0 += 8) {
        const int buf = (k0 >> 3) & 1;
        const bool more = (k0 + 8) < Hdim;
        if (more) {
            if (isB) { loadf8(pwi, gbi + k0 + 8); loadf8(pwh, gbh + k0 + 8); }
            else     { loadf8(pa, gax + k0 + 8); }
        }
        #pragma unroll
        for (int k = 0; k < 8; k++) {
            const float* ae = sAe + buf * 256 + k * 32 + aoff;
            const float* ah = sAh + buf * 256 + k * 32 + aoff;
            ulonglong2 ae01 = *reinterpret_cast<const ulonglong2*>(ae);
            ulonglong2 ae23 = *reinterpret_cast<const ulonglong2*>(ae + 4);
            ulonglong2 ah01 = *reinterpret_cast<const ulonglong2*>(ah);
            ulonglong2 ah23 = *reinterpret_cast<const ulonglong2*>(ah + 4);
            const float* bip = sBi + buf * 1536 + k * 192 + hl;
            const float* bhp = sBh + buf * 1536 + k * 192 + hl;
            #pragma unroll
            for (int g = 0; g < 3; g++) {
                ull bi = dup2(bip[g * 64]);
                ull bh = dup2(bhp[g * 64]);
                fma2(accI[0 * 3 + g], ae01.x, bi);
                fma2(accI[1 * 3 + g], ae01.y, bi);
                fma2(accI[2 * 3 + g], ae23.x, bi);
                fma2(accI[3 * 3 + g], ae23.y, bi);
                fma2(accH[0 * 3 + g], ah01.x, bh);
                fma2(accH[1 * 3 + g], ah01.y, bh);
                fma2(accH[2 * 3 + g], ah23.x, bh);
                fma2(accH[3 * 3 + g], ah23.y, bh);
            }
        }
        if (more) {
            const int nb = buf ^ 1;
            if (isB) {
                #pragma unroll
                for (int k = 0; k < 8; k++) {
                    sBi[nb * 1536 + k * 192 + tid] = pwi[k];
                    sBh[nb * 1536 + k * 192 + tid] = pwh[k];
                }
            } else {
                #pragma unroll
                for (int k = 0; k < 8; k++) aDst[nb * 256 + k * 32 + arow] = pa[k];
            }
        }
        __syncthreads();
    }

    // epilogue: gate combine in registers
    const float bir  = bih[h];
    const float biz  = bih[Hdim + h];
    const float bin_ = bih[2 * Hdim + h];
    const float bhr  = bhh[h];
    const float bhz  = bhh[Hdim + h];
    const float bhn  = bhh[2 * Hdim + h];
    #pragma unroll
    for (int mp = 0; mp < 4; mp++) {
        #pragma unroll
        for (int mm = 0; mm < 2; mm++) {
            int m = m0 + mpart * 8 + mp * 2 + mm;
            float ir  = pick(accI[mp * 3 + 0], mm) + bir;
            float iz  = pick(accI[mp * 3 + 1], mm) + biz;
            float in_ = pick(accI[mp * 3 + 2], mm) + bin_;
            float hr  = pick(accH[mp * 3 + 0], mm) + bhr;
            float hz  = pick(accH[mp * 3 + 1], mm) + bhz;
            float hn  = pick(accH[mp * 3 + 2], mm) + bhn;
            float r = 1.f / (1.f + expf(-(ir + hr)));
            float z = 1.f / (1.f + expf(-(iz + hz)));
            float n = tanhf(in_ + r * hn);
            float hprev = Hin[(size_t)m * Hdim + h];
            Hout[(size_t)m * Hdim + h] = (1.f - z) * n + z * hprev;
        }
    }
}

// ===== fused OUT + SAMPLE stage =====
// Block owns rows m = 4*bx .. 4*bx+3, ALL 512 cols. Logits -> smem + gmem, sample locally.
// acc layout: acc[ci*2 + mp] where mp = m-pair (rows 2mp, 2mp+1), ci = column (c0 / c0+32).
__device__ void out_sample_stage(const float* __restrict__ H2, const float* __restrict__ Wout,
                                 const float* __restrict__ bout, float* __restrict__ out,
                                 float* __restrict__ tokout, int t, float* smem) {
    const int tid = threadIdx.x, bx = blockIdx.x;
    const int m0 = bx * 4;
    float* sA = smem;            // [2][8][4]
    float* sB = smem + 64;       // [2][8][512]
    float* sL = smem + 64 + 8192; // [4][512]

    const int warp = tid >> 5, lane = tid & 31;
    const int c0 = warp * 64 + lane;   // col 0; also handles c0+32

    const float* gb0 = Wout + (size_t)c0 * Hdim;
    const float* gb1 = Wout + (size_t)(c0 + 32) * Hdim;
    const float* ga  = (tid < 4) ? H2 + (size_t)(m0 + tid) * Hdim : nullptr;

    ull acc[4];  // [ci*2 + mp]
    acc[0] = acc[1] = acc[2] = acc[3] = 0ull;

    float pw0[8], pw1[8], pa[8];
    loadf8(pw0, gb0); loadf8(pw1, gb1);
    if (tid < 4) loadf8(pa, ga);
    #pragma unroll
    for (int k = 0; k < 8; k++) {
        sB[k * 512 + c0] = pw0[k];
        sB[k * 512 + c0 + 32] = pw1[k];
    }
    if (tid < 4) {
        #pragma unroll
        for (int k = 0; k < 8; k++) sA[k * 4 + tid] = pa[k];
    }
    __syncthreads();

    #pragma unroll 1
    for (int k0 = 0; k0 < Hdim; k0 += 8) {
        const int buf = (k0 >> 3) & 1;
        const bool more = (k0 + 8) < Hdim;
        if (more) {
            loadf8(pw0, gb0 + k0 + 8);
            loadf8(pw1, gb1 + k0 + 8);
            if (tid < 4) loadf8(pa, ga + k0 + 8);
        }
        #pragma unroll
        for (int k = 0; k < 8; k++) {
            ulonglong2 aa = *reinterpret_cast<const ulonglong2*>(sA + buf * 32 + k * 4);
            ull b0 = dup2(sB[buf * 4096 + k * 512 + c0]);
            ull b1 = dup2(sB[buf * 4096 + k * 512 + c0 + 32]);
            fma2(acc[0], aa.x, b0);   // ci=0, mp=0 (rows 0,1)
            fma2(acc[1], aa.y, b0);   // ci=0, mp=1 (rows 2,3)
            fma2(acc[2], aa.x, b1);   // ci=1, mp=0
            fma2(acc[3], aa.y, b1);   // ci=1, mp=1
        }
        if (more) {
            const int nb = buf ^ 1;
            #pragma unroll
            for (int k = 0; k < 8; k++) {
                sB[nb * 4096 + k * 512 + c0] = pw0[k];
                sB[nb * 4096 + k * 512 + c0 + 32] = pw1[k];
            }
            if (tid < 4) {
                #pragma unroll
                for (int k = 0; k < 8; k++) sA[nb * 32 + k * 4 + tid] = pa[k];
            }
        }
        __syncthreads();
    }

    // epilogue: logits -> sL + gmem  (FIXED indexing: acc[ci*2 + mp], mm within pair)
    const float bb0 = bout[c0], bb1 = bout[c0 + 32];
    #pragma unroll
    for (int mp = 0; mp < 2; mp++) {
        #pragma unroll
        for (int mm = 0; mm < 2; mm++) {
            int r = mp * 2 + mm;
            int m = m0 + r;
            float v0 = pick(acc[0 * 2 + mp], mm) + bb0;
            float v1 = pick(acc[1 * 2 + mp], mm) + bb1;
            sL[r * 512 + c0] = v0;
            sL[r * 512 + c0 + 32] = v1;
            float* orow = out + (size_t)m * (Tdim * NCdim) + (size_t)t * NCdim;
            orow[c0] = v0;
            orow[c0 + 32] = v1;
        }
    }
    __syncthreads();

    // ---- sampling for the 4 local rows ----
    __shared__ float s_red[8];
    __shared__ float s_val[8];
    __shared__ int   s_idx[8];
    unsigned key0 = g_key0[t], key1 = g_key1[t];
    #pragma unroll 1
    for (int r = 0; r < 4; r++) {
        int b = m0 + r;
        const float* row = sL + r * 512;

        float mx = -3.402823466e38f;
        for (int c = tid; c < NCdim; c += NTHR) mx = fmaxf(mx, row[c]);
        #pragma unroll
        for (int o = 16; o; o >>= 1) mx = fmaxf(mx, __shfl_xor_sync(0xffffffffu, mx, o));
        if (lane == 0) s_red[warp] = mx;
        __syncthreads();
        float m2 = s_red[0];
        #pragma unroll
        for (int k = 1; k < 8; k++) m2 = fmaxf(m2, s_red[k]);
        mx = m2;
        __syncthreads();

        float s = 0.f;
        for (int c = tid; c < NCdim; c += NTHR) s += expf(row[c] - mx);
        #pragma unroll
        for (int o = 16; o; o >>= 1) s += __shfl_xor_sync(0xffffffffu, s, o);
        if (lane == 0) s_red[warp] = s;
        __syncthreads();
        float s2 = 0.f;
        #pragma unroll
        for (int k = 0; k < 8; k++) s2 += s_red[k];
        float lse = logf(s2);
        __syncthreads();

        float best = -3.402823466e38f;
        int bi = NCdim;
        const float tiny = 1.17549435e-38f;
        for (int c = tid; c < NCdim; c += NTHR) {
            unsigned j = (unsigned)(b * NCdim + c);
            unsigned o0, o1;
            threefry2x32(key0, key1, 0u, j, o0, o1);
            unsigned bits = o0 ^ o1;
            float f = __uint_as_float((bits >> 9) | 0x3F800000u) - 1.0f;
            float u = fmaxf(tiny, f + tiny);
            float g = -logf(-logf(u));
            float v = ((row[c] - mx) - lse) + g;
            if (v > best) { best = v; bi = c; }
        }
        #pragma unroll
        for (int o = 16; o; o >>= 1) {
            float ov = __shfl_xor_sync(0xffffffffu, best, o);
            int   oi = __shfl_xor_sync(0xffffffffu, bi, o);
            if (ov > best || (ov == best && oi < bi)) { best = ov; bi = oi; }
        }
        if (lane == 0) { s_val[warp] = best; s_idx[warp] = bi; }
        __syncthreads();
        if (tid == 0) {
            float bv = s_val[0]; int bidx = s_idx[0];
            #pragma unroll
            for (int k = 1; k < 8; k++) {
                if (s_val[k] > bv || (s_val[k] == bv && s_idx[k] < bidx)) {
                    bv = s_val[k]; bidx = s_idx[k];
                }
            }
            g_tok[b] = bidx;
            if (tokout) tokout[(size_t)b * Tdim + t] = (float)bidx;
        }
        __syncthreads();
    }
}

// ===== main persistent kernel =====
__global__ void __launch_bounds__(NTHR, 1)
prior_persistent(const float* __restrict__ note, const float* __restrict__ genre,
                 const float* __restrict__ Whid, const float* __restrict__ bhid,
                 const float* __restrict__ emb,
                 const float* __restrict__ Wih1, const float* __restrict__ Whh1,
                 const float* __restrict__ bih1, const float* __restrict__ bhh1,
                 const float* __restrict__ Wih2, const float* __restrict__ Whh2,
                 const float* __restrict__ bih2, const float* __restrict__ bhh2,
                 const float* __restrict__ Wout, const float* __restrict__ bout,
                 float* __restrict__ out, float* __restrict__ tokout) {
    extern __shared__ float smem[];
    const int tid = threadIdx.x, bx = blockIdx.x;

    // ---------- init ----------
    {
        int gidx = bx * NTHR + tid;
        if (gidx < Tdim) {
            unsigned o0, o1;
            threefry2x32(0u, 42u, 0u, (unsigned)gidx, o0, o1);
            g_key0[gidx] = o0; g_key1[gidx] = o1;
        }
        if (gidx < Bdim) g_tok[gidx] = 0;

        for (int r = 0; r < Bdim / NBLK; r++) {
            int b = bx * (Bdim / NBLK) + r;
            for (int i = tid; i < SKELdim; i += NTHR) smem[i] = note[b * SKELdim + i];
            for (int i = tid; i < GENdim; i += NTHR) smem[SKELdim + i] = genre[b * GENdim + i];
            __syncthreads();
            for (int j = tid; j < Hdim; j += NTHR) {
                const float* w = Whid + (size_t)j * (SKELdim + GENdim);
                float acc = 0.f;
                #pragma unroll 8
                for (int k = 0; k < SKELdim + GENdim; k++) acc = fmaf(smem[k], w[k], acc);
                g_h1a[(size_t)b * Hdim + j] = acc + bhid[j];
            }
            __syncthreads();
        }
    }
    grid_barrier();

    for (int t = 0; t < Tdim; t++) {
        const float* h1r; float* h1w; const float* h2r; float* h2w;
        if (t & 1) { h1r = g_h1b; h1w = g_h1a; h2r = g_h2b; h2w = g_h2a; }
        else       { h1r = g_h1a; h1w = g_h1b; h2r = g_h2a; h2w = g_h2b; }

        gru_stage<true>(emb, h1r, Wih1, Whh1, bih1, bhh1, h1w, smem);
        grid_barrier();

        const float* hp2 = (t == 0) ? (const float*)h1w : h2r;
        gru_stage<false>(h1w, hp2, Wih2, Whh2, bih2, bhh2, h2w, smem);
        grid_barrier();

        out_sample_stage(h2w, Wout, bout, out, tokout, t, smem);
        grid_barrier();
    }
}

// ===== launch: ONE graph node =====
extern "C" void kernel_launch(void* const* d_in, const int* in_sizes, int n_in,
                              void* d_out, int out_size) {
    const float* note  = (const float*)d_in[1];
    const float* genre = (const float*)d_in[2];
    const float* W_hid = (const float*)d_in[3];
    const float* b_hid = (const float*)d_in[4];
    const float* emb   = (const float*)d_in[5];
    const float* W_ih1 = (const float*)d_in[6];
    const float* W_hh1 = (const float*)d_in[7];
    const float* b_ih1 = (const float*)d_in[8];
    const float* b_hh1 = (const float*)d_in[9];
    const float* W_ih2 = (const float*)d_in[10];
    const float* W_hh2 = (const float*)d_in[11];
    const float* b_ih2 = (const float*)d_in[12];
    const float* b_hh2 = (const float*)d_in[13];
    const float* W_out = (const float*)d_in[14];
    const float* b_out = (const float*)d_in[15];

    float* out = (float*)d_out;
    const long long need = (long long)Bdim * Tdim * NCdim + (long long)Bdim * Tdim;
    float* tokout = ((long long)out_size >= need) ? (out + (size_t)Bdim * Tdim * NCdim) : nullptr;

    cudaFuncSetAttribute(prior_persistent,
                         cudaFuncAttributeMaxDynamicSharedMemorySize, SMEM_BYTES);

    prior_persistent<<<NBLK, NTHR, SMEM_BYTES>>>(note, genre, W_hid, b_hid, emb,
                                                 W_ih1, W_hh1, b_ih1, b_hh1,
                                                 W_ih2, W_hh2, b_ih2, b_hh2,
                                                 W_out, b_out, out, tokout);
}